// round 4
// baseline (speedup 1.0000x reference)
#include <cuda_runtime.h>
#include <cuda_bf16.h>

#define IN_DIM   512
#define BATCH    8192
#define GRID_NUM 48
#define NCOEF    (GRID_NUM + 3)   // 51
#define NKNOT    (GRID_NUM + 1)   // 49
#define TILE     64               // dims per block
#define THREADS  256              // 4 rows per block iteration
#define GY       128              // rows per step = GY*4 = 512 -> 16 rows/thread exact

// Per-(cell,dim) cubic monomial coefficients, laid out [cell][dim] for coalesced staging.
__device__ float4 g_poly[GRID_NUM * IN_DIM];
__device__ float  g_lo[IN_DIM];
__device__ float  g_invh[IN_DIM];

__global__ void prep_kernel(const float* __restrict__ grid,
                            const float* __restrict__ coef) {
    int k = blockIdx.x * blockDim.x + threadIdx.x;
    if (k < GRID_NUM * IN_DIM) {
        int cell = k >> 9;            // k / 512
        int dim  = k & (IN_DIM - 1);
        const float* c = coef + dim * NCOEF + cell;
        float c0 = c[0], c1 = c[1], c2 = c[2], c3 = c[3];
        float4 a;
        a.x = (c0 + 4.0f * c1 + c2) * (1.0f / 6.0f);
        a.y = (c2 - c0) * 0.5f;
        a.z = (c0 - 2.0f * c1 + c2) * 0.5f;
        a.w = (c3 - c0 + 3.0f * (c1 - c2)) * (1.0f / 6.0f);
        g_poly[k] = a;                // coalesced
    }
    if (k < IN_DIM) {
        float lo = grid[k * NKNOT];
        float hi = grid[k * NKNOT + GRID_NUM];
        g_lo[k]   = lo;
        g_invh[k] = (float)GRID_NUM / (hi - lo);
    }
}

__global__ __launch_bounds__(THREADS) void bspline_kernel(
    const float* __restrict__ x,
    float* __restrict__ y)
{
    __shared__ float4 s_quad[GRID_NUM * TILE];   // 48KB, [cell][d]: LDS.128 conflict-free

    const int tid  = threadIdx.x;
    const int dim0 = blockIdx.x * TILE;

    // Stage: 48 cells x 64 dims, coalesced float4 loads.
    #pragma unroll 4
    for (int k = tid; k < GRID_NUM * TILE; k += THREADS) {
        int cell = k >> 6, d = k & (TILE - 1);
        s_quad[k] = g_poly[cell * IN_DIM + dim0 + d];
    }

    const int d    = tid & (TILE - 1);
    const int rofs = tid >> 6;                   // 0..3
    const float lo   = g_lo[dim0 + d];
    const float invh = g_invh[dim0 + d];
    const int col = dim0 + d;
    const int b0  = blockIdx.y * 4 + rofs;

    __syncthreads();

    #pragma unroll
    for (int g = 0; g < 4; ++g) {
        float xv[4], res[4];
        #pragma unroll
        for (int q = 0; q < 4; ++q)              // batch streaming loads (MLP=4)
            xv[q] = x[(b0 + (g * 4 + q) * (GY * 4)) * IN_DIM + col];
        #pragma unroll
        for (int q = 0; q < 4; ++q) {
            float t = (xv[q] - lo) * invh;
            int cell = (int)t;                   // t >= 0 here; trunc == floor
            cell = max(0, min(cell, GRID_NUM - 1));
            float u = t - (float)cell;
            float4 a = s_quad[cell * TILE + d];  // single LDS.128, conflict-free
            res[q] = fmaf(fmaf(fmaf(a.w, u, a.z), u, a.y), u, a.x);
        }
        #pragma unroll
        for (int q = 0; q < 4; ++q)
            y[(b0 + (g * 4 + q) * (GY * 4)) * IN_DIM + col] = res[q];
    }
}

extern "C" void kernel_launch(void* const* d_in, const int* in_sizes, int n_in,
                              void* d_out, int out_size) {
    const float* x    = (const float*)d_in[0];
    const float* grid = (const float*)d_in[1];
    const float* coef = (const float*)d_in[2];
    float* y = (float*)d_out;

    prep_kernel<<<(GRID_NUM * IN_DIM + 255) / 256, 256>>>(grid, coef);

    dim3 g(IN_DIM / TILE, GY);                   // 8 x 128 = 1024 blocks
    bspline_kernel<<<g, THREADS>>>(x, y);
}

// round 5
// speedup vs baseline: 1.0690x; 1.0690x over previous
#include <cuda_runtime.h>
#include <cuda_bf16.h>

#define IN_DIM   512
#define BATCH    8192
#define GRID_NUM 48
#define NCOEF    (GRID_NUM + 3)   // 51
#define NKNOT    (GRID_NUM + 1)   // 49
#define TILE     32               // dims per block
#define THREADS  256              // 8 rows per block iteration
#define GY       64               // grid.y -> 16*64 = 1024 blocks
#define CELL_LO  24               // x in [0,1) -> t in [24,48): only cells 24..47 reachable
#define NCELL_S  24               // staged cells

// Per-(cell,dim) cubic monomial coefficients, [cell][dim] (full table: fallback source).
__device__ float4 g_poly[GRID_NUM * IN_DIM];
__device__ float  g_lo[IN_DIM];
__device__ float  g_invh[IN_DIM];

#define PREP_DIMS 16   // dims per prep block -> 32 blocks

__global__ void prep_kernel(const float* __restrict__ grid,
                            const float* __restrict__ coef) {
    __shared__ float s_c[PREP_DIMS * NCOEF];     // 816 floats
    const int tid  = threadIdx.x;
    const int dim0 = blockIdx.x * PREP_DIMS;

    for (int k = tid; k < PREP_DIMS * NCOEF; k += THREADS)
        s_c[k] = coef[dim0 * NCOEF + k];         // coalesced
    if (tid < PREP_DIMS) {
        int i = dim0 + tid;
        float lo = grid[i * NKNOT];
        float hi = grid[i * NKNOT + GRID_NUM];
        g_lo[i]   = lo;
        g_invh[i] = (float)GRID_NUM / (hi - lo);
    }
    __syncthreads();

    for (int k = tid; k < GRID_NUM * PREP_DIMS; k += THREADS) {
        int cell = k >> 4, d = k & (PREP_DIMS - 1);
        const float* c = s_c + d * NCOEF + cell;
        float c0 = c[0], c1 = c[1], c2 = c[2], c3 = c[3];
        float4 a;
        a.x = (c0 + 4.0f * c1 + c2) * (1.0f / 6.0f);
        a.y = (c2 - c0) * 0.5f;
        a.z = (c0 - 2.0f * c1 + c2) * 0.5f;
        a.w = (c3 - c0 + 3.0f * (c1 - c2)) * (1.0f / 6.0f);
        g_poly[cell * IN_DIM + dim0 + d] = a;    // coalesced-ish (256B runs)
    }
}

__global__ __launch_bounds__(THREADS, 6) void bspline_kernel(
    const float* __restrict__ x,
    float* __restrict__ y)
{
    __shared__ float4 s_quad[NCELL_S * TILE];    // 12 KB, [cell-24][d]: LDS.128 conflict-free

    const int tid  = threadIdx.x;
    const int dim0 = blockIdx.x * TILE;

    #pragma unroll
    for (int k = tid; k < NCELL_S * TILE; k += THREADS)
        s_quad[k] = g_poly[(CELL_LO + (k >> 5)) * IN_DIM + dim0 + (k & (TILE - 1))];

    const int d    = tid & (TILE - 1);
    const int rofs = tid >> 5;                   // 0..7
    const int col  = dim0 + d;
    const float lo   = g_lo[col];
    const float invh = g_invh[col];
    const int b0 = blockIdx.y * 8 + rofs;        // in [0, 512)

    __syncthreads();

    #pragma unroll
    for (int s = 0; s < 8; ++s) {
        float xv[2], res[2];
        #pragma unroll
        for (int q = 0; q < 2; ++q)              // MLP=2 streaming loads
            xv[q] = x[(b0 + (2 * s + q) * (GY * 8)) * IN_DIM + col];
        #pragma unroll
        for (int q = 0; q < 2; ++q) {
            float t = (xv[q] - lo) * invh;
            int cell = (int)t;                   // t >= 0 in-domain; trunc == floor
            cell = max(0, min(cell, GRID_NUM - 1));
            float u = t - (float)cell;
            float4 a;
            int cs = cell - CELL_LO;
            if ((unsigned)cs < (unsigned)NCELL_S)
                a = s_quad[cs * TILE + d];       // hot path: conflict-free LDS.128
            else
                a = g_poly[cell * IN_DIM + col]; // never taken for in-range inputs
            res[q] = fmaf(fmaf(fmaf(a.w, u, a.z), u, a.y), u, a.x);
        }
        #pragma unroll
        for (int q = 0; q < 2; ++q)
            y[(b0 + (2 * s + q) * (GY * 8)) * IN_DIM + col] = res[q];
    }
}

extern "C" void kernel_launch(void* const* d_in, const int* in_sizes, int n_in,
                              void* d_out, int out_size) {
    const float* x    = (const float*)d_in[0];
    const float* grid = (const float*)d_in[1];
    const float* coef = (const float*)d_in[2];
    float* y = (float*)d_out;

    prep_kernel<<<IN_DIM / PREP_DIMS, THREADS>>>(grid, coef);

    dim3 g(IN_DIM / TILE, GY);                   // 16 x 64 = 1024 blocks
    bspline_kernel<<<g, THREADS>>>(x, y);
}